// round 1
// baseline (speedup 1.0000x reference)
#include <cuda_runtime.h>
#include <cstdint>

#define N_NODES 64000
#define NPOINTS 2000
#define NB 32
#define TT 12
#define E_EDGES 1024000
#define GH 32
#define NO 8
#define HH 64
#define CHUNK 256
#define LOOKBACK 256
#define NCHUNK (N_NODES / CHUNK)   // 250

// scratch (static device globals; no allocation at runtime)
__device__ float g_x11[N_NODES];
__device__ float g_agg1[N_NODES];
__device__ float g_y[N_NODES * NO];
__device__ float g_acc[N_NODES * NO];
__device__ float g_wt[NB];

// ---------------------------------------------------------------------------
// K1: extract x at t=11 in node order, zero agg1, compute weather/time scalar
// ---------------------------------------------------------------------------
__global__ void prep_kernel(const float* __restrict__ x,
                            const float* __restrict__ weather,
                            const float* __restrict__ timeenc,
                            const float* __restrict__ Wlin,
                            const float* __restrict__ blin) {
    int n = blockIdx.x * blockDim.x + threadIdx.x;
    if (n < N_NODES) {
        int b = n / NPOINTS;
        int p = n - b * NPOINTS;
        g_x11[n] = x[b * (TT * NPOINTS) + 11 * NPOINTS + p];
        g_agg1[n] = 0.f;
    }
    if (blockIdx.x == 0 && threadIdx.x < NB) {
        int b = threadIdx.x;
        float s = blin[0];
        #pragma unroll
        for (int j = 0; j < 4; j++)
            s += weather[b * TT * 4 + 11 * 4 + j] * Wlin[64 + j];
        #pragma unroll
        for (int j = 0; j < 8; j++)
            s += timeenc[b * TT * 8 + 11 * 8 + j] * Wlin[68 + j];
        g_wt[b] = s;
    }
}

// ---------------------------------------------------------------------------
// K2: agg1[dst] += x11[src]  (scalar segment sum over 1M edges, 4 edges/thread)
// ---------------------------------------------------------------------------
__global__ void scatter1_kernel(const int* __restrict__ ei) {
    int i = blockIdx.x * blockDim.x + threadIdx.x;
    if (i * 4 >= E_EDGES) return;
    int4 s4 = ((const int4*)ei)[i];
    int4 d4 = ((const int4*)(ei + E_EDGES))[i];
    atomicAdd(&g_agg1[d4.x], __ldg(&g_x11[s4.x]));
    atomicAdd(&g_agg1[d4.y], __ldg(&g_x11[s4.y]));
    atomicAdd(&g_agg1[d4.z], __ldg(&g_x11[s4.z]));
    atomicAdd(&g_agg1[d4.w], __ldg(&g_x11[s4.w]));
}

// ---------------------------------------------------------------------------
// K3: per node: h1 = relu(agg1*W1rel + x*W1root + b1) (32-vec)
//     y   = h1 @ W2rel            (8-vec, to be edge-aggregated)
//     acc = h1 @ W2root + b2      (8-vec, root part; acc becomes lstm_in[11])
//     out[n] = wt[n % 32]         (init output with weather/time/bias part)
// ---------------------------------------------------------------------------
__global__ void node_kernel(const float* __restrict__ W1rel,
                            const float* __restrict__ b1,
                            const float* __restrict__ W1root,
                            const float* __restrict__ W2rel,
                            const float* __restrict__ b2,
                            const float* __restrict__ W2root,
                            float* __restrict__ out) {
    __shared__ float sW1rel[GH], sb1[GH], sW1root[GH];
    __shared__ float sW2rel[GH * NO], sW2root[GH * NO], sb2[NO];
    int tid = threadIdx.x;
    if (tid < GH) {
        sW1rel[tid] = W1rel[tid];
        sb1[tid] = b1[tid];
        sW1root[tid] = W1root[tid];
    }
    if (tid < GH * NO) {
        sW2rel[tid] = W2rel[tid];
        sW2root[tid] = W2root[tid];
    }
    if (tid < NO) sb2[tid] = b2[tid];
    __syncthreads();

    int n = blockIdx.x * blockDim.x + tid;
    if (n >= N_NODES) return;
    float a = g_agg1[n];
    float xv = g_x11[n];
    float y[NO], p[NO];
    #pragma unroll
    for (int j = 0; j < NO; j++) { y[j] = 0.f; p[j] = sb2[j]; }
    #pragma unroll
    for (int k = 0; k < GH; k++) {
        float h1 = fmaf(a, sW1rel[k], fmaf(xv, sW1root[k], sb1[k]));
        h1 = fmaxf(h1, 0.f);
        #pragma unroll
        for (int j = 0; j < NO; j++) {
            y[j] = fmaf(h1, sW2rel[k * NO + j], y[j]);
            p[j] = fmaf(h1, sW2root[k * NO + j], p[j]);
        }
    }
    float4* yp = (float4*)&g_y[n * NO];
    yp[0] = make_float4(y[0], y[1], y[2], y[3]);
    yp[1] = make_float4(y[4], y[5], y[6], y[7]);
    float4* ap = (float4*)&g_acc[n * NO];
    ap[0] = make_float4(p[0], p[1], p[2], p[3]);
    ap[1] = make_float4(p[4], p[5], p[6], p[7]);
    out[n] = g_wt[n & (NB - 1)];
}

// ---------------------------------------------------------------------------
// K4: acc[dst] += y[src]   (8 floats/edge, vector reductions)
// ---------------------------------------------------------------------------
__device__ __forceinline__ void red_add_v4(float* addr, float4 v) {
    asm volatile("red.global.add.v4.f32 [%0], {%1,%2,%3,%4};"
                 :: "l"(addr), "f"(v.x), "f"(v.y), "f"(v.z), "f"(v.w)
                 : "memory");
}

__global__ void scatter2_kernel(const int* __restrict__ ei) {
    int e = blockIdx.x * blockDim.x + threadIdx.x;
    if (e >= E_EDGES) return;
    int s = __ldg(&ei[e]);
    int d = __ldg(&ei[E_EDGES + e]);
    const float4* yp = (const float4*)&g_y[s * NO];
    float4 va = __ldg(yp);
    float4 vb = __ldg(yp + 1);
    red_add_v4(&g_acc[d * NO], va);
    red_add_v4(&g_acc[d * NO + 4], vb);
}

// ---------------------------------------------------------------------------
// K5: chunked LSTM scan over the node axis (only carry row t=11 matters).
// 250 blocks, each: LOOKBACK warm-up + CHUNK output steps.
// 256 threads: warp w owns hidden units [8w, 8w+8); lane l -> unit w*8+(l>>2),
// gate type l&3 (0:i 1:f 2:g 3:o), gate index = (l&3)*64 + unit.
// ---------------------------------------------------------------------------
__global__ void __launch_bounds__(256, 2) lstm_kernel(
    const float* __restrict__ Wih, const float* __restrict__ Whh,
    const float* __restrict__ bih, const float* __restrict__ bhh,
    const float* __restrict__ Wlin, float* __restrict__ out) {
    __shared__ __align__(16) float hbuf[2][HH];
    __shared__ __align__(16) float xtile[64 * NO];   // 64 nodes staged

    int tid = threadIdx.x;
    int l = tid & 31;
    int w = tid >> 5;
    int j = w * 8 + (l >> 2);   // hidden unit
    int gt = l & 3;             // gate type
    int gidx = gt * 64 + j;

    float whh[HH];
    #pragma unroll
    for (int k = 0; k < HH; k++) whh[k] = __ldg(&Whh[k * 256 + gidx]);
    float wih[NO];
    #pragma unroll
    for (int k = 0; k < NO; k++) wih[k] = __ldg(&Wih[k * 256 + gidx]);
    float bsum = __ldg(&bih[gidx]) + __ldg(&bhh[gidx]);
    float wl = __ldg(&Wlin[j]);

    if (tid < HH) hbuf[0][tid] = 0.f;

    int start = blockIdx.x * CHUNK;
    int s0 = start - LOOKBACK;
    if (s0 < 0) s0 = 0;
    int end = start + CHUNK;

    float c = 0.f;
    int cur = 0;
    __syncthreads();

    for (int n = s0; n < end; n++) {
        int off = (n - s0) & 63;
        if (off == 0) {
            // previous iteration's __syncthreads() makes the overwrite safe
            xtile[tid]       = g_acc[n * NO + tid];
            xtile[tid + 256] = g_acc[n * NO + 256 + tid];
            __syncthreads();
        }
        float4 xa = *(const float4*)&xtile[off * NO];
        float4 xb = *(const float4*)&xtile[off * NO + 4];
        float a0 = bsum, a1 = 0.f, a2 = 0.f, a3 = 0.f;
        a0 = fmaf(xa.x, wih[0], a0); a1 = fmaf(xa.y, wih[1], a1);
        a2 = fmaf(xa.z, wih[2], a2); a3 = fmaf(xa.w, wih[3], a3);
        a0 = fmaf(xb.x, wih[4], a0); a1 = fmaf(xb.y, wih[5], a1);
        a2 = fmaf(xb.z, wih[6], a2); a3 = fmaf(xb.w, wih[7], a3);
        const float4* hp = (const float4*)hbuf[cur];
        #pragma unroll
        for (int k = 0; k < 16; k++) {
            float4 h4 = hp[k];   // broadcast LDS.128
            a0 = fmaf(h4.x, whh[4 * k + 0], a0);
            a1 = fmaf(h4.y, whh[4 * k + 1], a1);
            a2 = fmaf(h4.z, whh[4 * k + 2], a2);
            a3 = fmaf(h4.w, whh[4 * k + 3], a3);
        }
        float g = (a0 + a1) + (a2 + a3);
        // act = sigmoid(g) for i,f,o ; tanh(g) for gate type 2 (single exp path)
        float scale = (gt == 2) ? 2.f : 1.f;
        float sg = 1.f / (1.f + __expf(-scale * g));
        float act = (gt == 2) ? (2.f * sg - 1.f) : sg;

        unsigned base = (unsigned)(l & ~3);
        float iv = __shfl_sync(0xffffffffu, act, base + 0);
        float fv = __shfl_sync(0xffffffffu, act, base + 1);
        float gv = __shfl_sync(0xffffffffu, act, base + 2);
        float ov = __shfl_sync(0xffffffffu, act, base + 3);
        c = fv * c + iv * gv;                 // all 4 lanes keep identical c
        float tc = 2.f / (1.f + __expf(-2.f * c)) - 1.f;   // tanh(c)
        float hn = ov * tc;

        int nxt = cur ^ 1;
        if (gt == 0) hbuf[nxt][j] = hn;

        if (n >= start) {
            float p = (gt == 0) ? hn * wl : 0.f;
            p += __shfl_xor_sync(0xffffffffu, p, 16);
            p += __shfl_xor_sync(0xffffffffu, p, 8);
            p += __shfl_xor_sync(0xffffffffu, p, 4);
            if (l == 0) atomicAdd(&out[n], p);   // 8 warps accumulate dot(h,Wlin)
        }
        cur = nxt;
        __syncthreads();
    }
}

// ---------------------------------------------------------------------------
extern "C" void kernel_launch(void* const* d_in, const int* in_sizes, int n_in,
                              void* d_out, int out_size) {
    const float* x        = (const float*)d_in[0];
    const int*   ei       = (const int*)  d_in[1];
    const float* weather  = (const float*)d_in[2];
    const float* timeenc  = (const float*)d_in[3];
    // d_in[4] W1rel, 5 b1, 6 W1root, 7 W2rel, 8 b2, 9 W2root
    const float* W1rel    = (const float*)d_in[4];
    const float* b1       = (const float*)d_in[5];
    const float* W1root   = (const float*)d_in[6];
    const float* W2rel    = (const float*)d_in[7];
    const float* b2       = (const float*)d_in[8];
    const float* W2root   = (const float*)d_in[9];
    const float* Wih      = (const float*)d_in[10];
    const float* Whh      = (const float*)d_in[11];
    const float* bih      = (const float*)d_in[12];
    const float* bhh      = (const float*)d_in[13];
    const float* Wlin     = (const float*)d_in[14];
    const float* blin     = (const float*)d_in[15];
    float* out = (float*)d_out;

    prep_kernel<<<(N_NODES + 255) / 256, 256>>>(x, weather, timeenc, Wlin, blin);
    scatter1_kernel<<<(E_EDGES / 4 + 255) / 256, 256>>>(ei);
    node_kernel<<<(N_NODES + 255) / 256, 256>>>(W1rel, b1, W1root, W2rel, b2, W2root, out);
    scatter2_kernel<<<(E_EDGES + 255) / 256, 256>>>(ei);
    lstm_kernel<<<NCHUNK, 256>>>(Wih, Whh, bih, bhh, Wlin, out);
}

// round 2
// speedup vs baseline: 1.1118x; 1.1118x over previous
#include <cuda_runtime.h>
#include <cstdint>

#define N_NODES 64000
#define NPOINTS 2000
#define NB 32
#define TT 12
#define E_EDGES 1024000
#define GH 32
#define NO 8
#define HH 64
#define NBLK 148
#define CHUNK 433            // ceil(64000/148)
#define LOOKBACK 128

// scratch (static device globals; no allocation at runtime)
__device__ float g_x11[N_NODES];
__device__ float g_agg1[N_NODES];
__device__ float g_y[N_NODES * NO];
__device__ float g_acc[(N_NODES + 64) * NO];   // +64 nodes pad for staging reads
__device__ float g_wt[NB];

// ---- packed f32x2 helpers -------------------------------------------------
__device__ __forceinline__ unsigned long long pack2(float lo, float hi) {
    unsigned long long r;
    asm("mov.b64 %0, {%1,%2};" : "=l"(r) : "f"(lo), "f"(hi));
    return r;
}
__device__ __forceinline__ unsigned long long fma2(unsigned long long a,
                                                   unsigned long long b,
                                                   unsigned long long c) {
    unsigned long long d;
    asm("fma.rn.f32x2 %0, %1, %2, %3;" : "=l"(d) : "l"(a), "l"(b), "l"(c));
    return d;
}
__device__ __forceinline__ float unpack_sum(unsigned long long v) {
    float lo, hi;
    asm("mov.b64 {%0,%1}, %2;" : "=f"(lo), "=f"(hi) : "l"(v));
    return lo + hi;
}

// ---------------------------------------------------------------------------
// K1: extract x at t=11 in node order, zero agg1, compute weather/time scalar
// ---------------------------------------------------------------------------
__global__ void prep_kernel(const float* __restrict__ x,
                            const float* __restrict__ weather,
                            const float* __restrict__ timeenc,
                            const float* __restrict__ Wlin,
                            const float* __restrict__ blin) {
    int n = blockIdx.x * blockDim.x + threadIdx.x;
    if (n < N_NODES) {
        int b = n / NPOINTS;
        int p = n - b * NPOINTS;
        g_x11[n] = x[b * (TT * NPOINTS) + 11 * NPOINTS + p];
        g_agg1[n] = 0.f;
    }
    if (blockIdx.x == 0 && threadIdx.x < NB) {
        int b = threadIdx.x;
        float s = blin[0];
        #pragma unroll
        for (int j = 0; j < 4; j++)
            s += weather[b * TT * 4 + 11 * 4 + j] * Wlin[64 + j];
        #pragma unroll
        for (int j = 0; j < 8; j++)
            s += timeenc[b * TT * 8 + 11 * 8 + j] * Wlin[68 + j];
        g_wt[b] = s;
    }
}

// ---------------------------------------------------------------------------
// K2: agg1[dst] += x11[src]
// ---------------------------------------------------------------------------
__global__ void scatter1_kernel(const int* __restrict__ ei) {
    int i = blockIdx.x * blockDim.x + threadIdx.x;
    if (i * 4 >= E_EDGES) return;
    int4 s4 = ((const int4*)ei)[i];
    int4 d4 = ((const int4*)(ei + E_EDGES))[i];
    atomicAdd(&g_agg1[d4.x], __ldg(&g_x11[s4.x]));
    atomicAdd(&g_agg1[d4.y], __ldg(&g_x11[s4.y]));
    atomicAdd(&g_agg1[d4.z], __ldg(&g_x11[s4.z]));
    atomicAdd(&g_agg1[d4.w], __ldg(&g_x11[s4.w]));
}

// ---------------------------------------------------------------------------
// K3: node MLP; writes y (edge payload), acc (root part), out init
// ---------------------------------------------------------------------------
__global__ void node_kernel(const float* __restrict__ W1rel,
                            const float* __restrict__ b1,
                            const float* __restrict__ W1root,
                            const float* __restrict__ W2rel,
                            const float* __restrict__ b2,
                            const float* __restrict__ W2root,
                            float* __restrict__ out) {
    __shared__ float sW1rel[GH], sb1[GH], sW1root[GH];
    __shared__ float sW2rel[GH * NO], sW2root[GH * NO], sb2[NO];
    int tid = threadIdx.x;
    if (tid < GH) {
        sW1rel[tid] = W1rel[tid];
        sb1[tid] = b1[tid];
        sW1root[tid] = W1root[tid];
    }
    if (tid < GH * NO) {
        sW2rel[tid] = W2rel[tid];
        sW2root[tid] = W2root[tid];
    }
    if (tid < NO) sb2[tid] = b2[tid];
    __syncthreads();

    int n = blockIdx.x * blockDim.x + tid;
    if (n >= N_NODES) return;
    float a = g_agg1[n];
    float xv = g_x11[n];
    float y[NO], p[NO];
    #pragma unroll
    for (int j = 0; j < NO; j++) { y[j] = 0.f; p[j] = sb2[j]; }
    #pragma unroll
    for (int k = 0; k < GH; k++) {
        float h1 = fmaf(a, sW1rel[k], fmaf(xv, sW1root[k], sb1[k]));
        h1 = fmaxf(h1, 0.f);
        #pragma unroll
        for (int j = 0; j < NO; j++) {
            y[j] = fmaf(h1, sW2rel[k * NO + j], y[j]);
            p[j] = fmaf(h1, sW2root[k * NO + j], p[j]);
        }
    }
    float4* yp = (float4*)&g_y[n * NO];
    yp[0] = make_float4(y[0], y[1], y[2], y[3]);
    yp[1] = make_float4(y[4], y[5], y[6], y[7]);
    float4* ap = (float4*)&g_acc[n * NO];
    ap[0] = make_float4(p[0], p[1], p[2], p[3]);
    ap[1] = make_float4(p[4], p[5], p[6], p[7]);
    out[n] = g_wt[n & (NB - 1)];
}

// ---------------------------------------------------------------------------
// K4: acc[dst] += y[src]   (8 floats/edge, vector reductions)
// ---------------------------------------------------------------------------
__device__ __forceinline__ void red_add_v4(float* addr, float4 v) {
    asm volatile("red.global.add.v4.f32 [%0], {%1,%2,%3,%4};"
                 :: "l"(addr), "f"(v.x), "f"(v.y), "f"(v.z), "f"(v.w)
                 : "memory");
}

__global__ void scatter2_kernel(const int* __restrict__ ei) {
    int e = blockIdx.x * blockDim.x + threadIdx.x;
    if (e >= E_EDGES) return;
    int s = __ldg(&ei[e]);
    int d = __ldg(&ei[E_EDGES + e]);
    const float4* yp = (const float4*)&g_y[s * NO];
    float4 va = __ldg(yp);
    float4 vb = __ldg(yp + 1);
    red_add_v4(&g_acc[d * NO], va);
    red_add_v4(&g_acc[d * NO + 4], vb);
}

// ---------------------------------------------------------------------------
// K5: chunked LSTM scan, 1 block per SM, f32x2-packed gate matvec.
// 256 threads: warp w owns hidden units [8w,8w+8); lane l -> unit w*8+(l>>2),
// gate type l&3 (0:i 1:f 2:g 3:o), gate index = (l&3)*64 + unit.
// ---------------------------------------------------------------------------
__global__ void __launch_bounds__(256, 1) lstm_kernel(
    const float* __restrict__ Wih, const float* __restrict__ Whh,
    const float* __restrict__ bih, const float* __restrict__ bhh,
    const float* __restrict__ Wlin, float* __restrict__ out) {
    __shared__ __align__(16) float hbuf[2][HH];
    __shared__ __align__(16) float xtile[64 * NO];   // 64 nodes staged

    int tid = threadIdx.x;
    int l = tid & 31;
    int w = tid >> 5;
    int j = w * 8 + (l >> 2);   // hidden unit
    int gt = l & 3;             // gate type
    int gidx = gt * 64 + j;

    // packed weights: whh2[k] = (Whh[2k][g], Whh[2k+1][g])
    unsigned long long whh2[HH / 2];
    #pragma unroll
    for (int k = 0; k < HH / 2; k++)
        whh2[k] = pack2(__ldg(&Whh[(2 * k) * 256 + gidx]),
                        __ldg(&Whh[(2 * k + 1) * 256 + gidx]));
    unsigned long long wih2[NO / 2];
    #pragma unroll
    for (int k = 0; k < NO / 2; k++)
        wih2[k] = pack2(__ldg(&Wih[(2 * k) * 256 + gidx]),
                        __ldg(&Wih[(2 * k + 1) * 256 + gidx]));
    float bsum = __ldg(&bih[gidx]) + __ldg(&bhh[gidx]);
    float wl = __ldg(&Wlin[j]);

    if (tid < HH) hbuf[0][tid] = 0.f;

    int start = blockIdx.x * CHUNK;
    int end = start + CHUNK;
    if (end > N_NODES) end = N_NODES;
    if (start >= N_NODES) return;   // (never true with NBLK=148, kept for safety)
    int s0 = start - LOOKBACK;
    if (s0 < 0) s0 = 0;

    float c = 0.f;
    int cur = 0;
    __syncthreads();

    for (int n = s0; n < end; n++) {
        int off = (n - s0) & 63;
        if (off == 0) {
            // previous iteration's __syncthreads() makes the overwrite safe
            xtile[tid]       = g_acc[n * NO + tid];
            xtile[tid + 256] = g_acc[n * NO + 256 + tid];
            __syncthreads();
        }
        // x contribution (4 packed fma) + h contribution (32 packed fma)
        const ulonglong2* xp = (const ulonglong2*)&xtile[off * NO];
        ulonglong2 xv0 = xp[0];
        ulonglong2 xv1 = xp[1];
        unsigned long long a0 = pack2(bsum, 0.f);
        unsigned long long a1 = pack2(0.f, 0.f);
        unsigned long long a2 = pack2(0.f, 0.f);
        unsigned long long a3 = pack2(0.f, 0.f);
        a0 = fma2(xv0.x, wih2[0], a0);
        a1 = fma2(xv0.y, wih2[1], a1);
        a2 = fma2(xv1.x, wih2[2], a2);
        a3 = fma2(xv1.y, wih2[3], a3);
        const ulonglong2* hp = (const ulonglong2*)hbuf[cur];
        #pragma unroll
        for (int k = 0; k < 16; k += 2) {
            ulonglong2 h4a = hp[k];
            ulonglong2 h4b = hp[k + 1];
            a0 = fma2(h4a.x, whh2[2 * k + 0], a0);
            a1 = fma2(h4a.y, whh2[2 * k + 1], a1);
            a2 = fma2(h4b.x, whh2[2 * k + 2], a2);
            a3 = fma2(h4b.y, whh2[2 * k + 3], a3);
        }
        float g = (unpack_sum(a0) + unpack_sum(a1)) +
                  (unpack_sum(a2) + unpack_sum(a3));
        // act = sigmoid(g) for i,f,o ; tanh(g) for gate type 2
        float scale = (gt == 2) ? 2.f : 1.f;
        float sg = 1.f / (1.f + __expf(-scale * g));
        float act = (gt == 2) ? (2.f * sg - 1.f) : sg;

        unsigned base = (unsigned)(l & ~3);
        float iv = __shfl_sync(0xffffffffu, act, base + 0);
        float fv = __shfl_sync(0xffffffffu, act, base + 1);
        float gv = __shfl_sync(0xffffffffu, act, base + 2);
        float ov = __shfl_sync(0xffffffffu, act, base + 3);
        c = fv * c + iv * gv;                 // all 4 lanes keep identical c
        float tc = 2.f / (1.f + __expf(-2.f * c)) - 1.f;   // tanh(c)
        float hn = ov * tc;

        int nxt = cur ^ 1;
        if (gt == 0) hbuf[nxt][j] = hn;

        if (n >= start) {
            float p = (gt == 0) ? hn * wl : 0.f;
            p += __shfl_xor_sync(0xffffffffu, p, 16);
            p += __shfl_xor_sync(0xffffffffu, p, 8);
            p += __shfl_xor_sync(0xffffffffu, p, 4);
            if (l == 0) atomicAdd(&out[n], p);   // 8 warps accumulate dot(h,Wlin)
        }
        cur = nxt;
        __syncthreads();
    }
}

// ---------------------------------------------------------------------------
extern "C" void kernel_launch(void* const* d_in, const int* in_sizes, int n_in,
                              void* d_out, int out_size) {
    const float* x        = (const float*)d_in[0];
    const int*   ei       = (const int*)  d_in[1];
    const float* weather  = (const float*)d_in[2];
    const float* timeenc  = (const float*)d_in[3];
    const float* W1rel    = (const float*)d_in[4];
    const float* b1       = (const float*)d_in[5];
    const float* W1root   = (const float*)d_in[6];
    const float* W2rel    = (const float*)d_in[7];
    const float* b2       = (const float*)d_in[8];
    const float* W2root   = (const float*)d_in[9];
    const float* Wih      = (const float*)d_in[10];
    const float* Whh      = (const float*)d_in[11];
    const float* bih      = (const float*)d_in[12];
    const float* bhh      = (const float*)d_in[13];
    const float* Wlin     = (const float*)d_in[14];
    const float* blin     = (const float*)d_in[15];
    float* out = (float*)d_out;

    prep_kernel<<<(N_NODES + 255) / 256, 256>>>(x, weather, timeenc, Wlin, blin);
    scatter1_kernel<<<(E_EDGES / 4 + 255) / 256, 256>>>(ei);
    node_kernel<<<(N_NODES + 255) / 256, 256>>>(W1rel, b1, W1root, W2rel, b2, W2root, out);
    scatter2_kernel<<<(E_EDGES + 255) / 256, 256>>>(ei);
    lstm_kernel<<<NBLK, 256>>>(Wih, Whh, bih, bhh, Wlin, out);
}

// round 3
// speedup vs baseline: 2.1610x; 1.9437x over previous
#include <cuda_runtime.h>
#include <cstdint>

#define N_NODES 64000
#define NPOINTS 2000
#define NB 32
#define TT 12
#define E_EDGES 1024000
#define GH 32
#define NO 8
#define HH 64
#define NBLK 148
#define NCHUNKS 296          // 2 groups per block
#define CHUNK 217            // ceil(64000/296)
#define LOOKBACK 96

// scratch (static device globals; no allocation at runtime)
__device__ float g_x11[N_NODES];
__device__ float g_agg1[N_NODES];
__device__ float g_y[N_NODES * NO];
__device__ float g_acc[(N_NODES + 64) * NO];   // +64 nodes pad for staging reads
__device__ float g_wt[NB];

// ---- packed f32x2 helpers -------------------------------------------------
__device__ __forceinline__ unsigned long long pack2(float lo, float hi) {
    unsigned long long r;
    asm("mov.b64 %0, {%1,%2};" : "=l"(r) : "f"(lo), "f"(hi));
    return r;
}
__device__ __forceinline__ unsigned long long fma2(unsigned long long a,
                                                   unsigned long long b,
                                                   unsigned long long c) {
    unsigned long long d;
    asm("fma.rn.f32x2 %0, %1, %2, %3;" : "=l"(d) : "l"(a), "l"(b), "l"(c));
    return d;
}
__device__ __forceinline__ float unpack_sum(unsigned long long v) {
    float lo, hi;
    asm("mov.b64 {%0,%1}, %2;" : "=f"(lo), "=f"(hi) : "l"(v));
    return lo + hi;
}
__device__ __forceinline__ float tanh_a(float x) {
    float y;
    asm("tanh.approx.f32 %0, %1;" : "=f"(y) : "f"(x));
    return y;
}

// ---------------------------------------------------------------------------
// K1: extract x at t=11 in node order, zero agg1, compute weather/time scalar
// ---------------------------------------------------------------------------
__global__ void prep_kernel(const float* __restrict__ x,
                            const float* __restrict__ weather,
                            const float* __restrict__ timeenc,
                            const float* __restrict__ Wlin,
                            const float* __restrict__ blin) {
    int n = blockIdx.x * blockDim.x + threadIdx.x;
    if (n < N_NODES) {
        int b = n / NPOINTS;
        int p = n - b * NPOINTS;
        g_x11[n] = x[b * (TT * NPOINTS) + 11 * NPOINTS + p];
        g_agg1[n] = 0.f;
    }
    if (blockIdx.x == 0 && threadIdx.x < NB) {
        int b = threadIdx.x;
        float s = blin[0];
        #pragma unroll
        for (int j = 0; j < 4; j++)
            s += weather[b * TT * 4 + 11 * 4 + j] * Wlin[64 + j];
        #pragma unroll
        for (int j = 0; j < 8; j++)
            s += timeenc[b * TT * 8 + 11 * 8 + j] * Wlin[68 + j];
        g_wt[b] = s;
    }
}

// ---------------------------------------------------------------------------
// K2: agg1[dst] += x11[src]
// ---------------------------------------------------------------------------
__global__ void scatter1_kernel(const int* __restrict__ ei) {
    int i = blockIdx.x * blockDim.x + threadIdx.x;
    if (i * 4 >= E_EDGES) return;
    int4 s4 = ((const int4*)ei)[i];
    int4 d4 = ((const int4*)(ei + E_EDGES))[i];
    atomicAdd(&g_agg1[d4.x], __ldg(&g_x11[s4.x]));
    atomicAdd(&g_agg1[d4.y], __ldg(&g_x11[s4.y]));
    atomicAdd(&g_agg1[d4.z], __ldg(&g_x11[s4.z]));
    atomicAdd(&g_agg1[d4.w], __ldg(&g_x11[s4.w]));
}

// ---------------------------------------------------------------------------
// K3: node MLP; writes y (edge payload), acc (root part), out init (= wt)
// ---------------------------------------------------------------------------
__global__ void node_kernel(const float* __restrict__ W1rel,
                            const float* __restrict__ b1,
                            const float* __restrict__ W1root,
                            const float* __restrict__ W2rel,
                            const float* __restrict__ b2,
                            const float* __restrict__ W2root,
                            float* __restrict__ out) {
    __shared__ float sW1rel[GH], sb1[GH], sW1root[GH];
    __shared__ float sW2rel[GH * NO], sW2root[GH * NO], sb2[NO];
    int tid = threadIdx.x;
    if (tid < GH) {
        sW1rel[tid] = W1rel[tid];
        sb1[tid] = b1[tid];
        sW1root[tid] = W1root[tid];
    }
    if (tid < GH * NO) {
        sW2rel[tid] = W2rel[tid];
        sW2root[tid] = W2root[tid];
    }
    if (tid < NO) sb2[tid] = b2[tid];
    __syncthreads();

    int n = blockIdx.x * blockDim.x + tid;
    if (n >= N_NODES) return;
    float a = g_agg1[n];
    float xv = g_x11[n];
    float y[NO], p[NO];
    #pragma unroll
    for (int j = 0; j < NO; j++) { y[j] = 0.f; p[j] = sb2[j]; }
    #pragma unroll
    for (int k = 0; k < GH; k++) {
        float h1 = fmaf(a, sW1rel[k], fmaf(xv, sW1root[k], sb1[k]));
        h1 = fmaxf(h1, 0.f);
        #pragma unroll
        for (int j = 0; j < NO; j++) {
            y[j] = fmaf(h1, sW2rel[k * NO + j], y[j]);
            p[j] = fmaf(h1, sW2root[k * NO + j], p[j]);
        }
    }
    float4* yp = (float4*)&g_y[n * NO];
    yp[0] = make_float4(y[0], y[1], y[2], y[3]);
    yp[1] = make_float4(y[4], y[5], y[6], y[7]);
    float4* ap = (float4*)&g_acc[n * NO];
    ap[0] = make_float4(p[0], p[1], p[2], p[3]);
    ap[1] = make_float4(p[4], p[5], p[6], p[7]);
    out[n] = g_wt[n & (NB - 1)];
}

// ---------------------------------------------------------------------------
// K4: acc[dst] += y[src]   (8 floats/edge, vector reductions)
// ---------------------------------------------------------------------------
__device__ __forceinline__ void red_add_v4(float* addr, float4 v) {
    asm volatile("red.global.add.v4.f32 [%0], {%1,%2,%3,%4};"
                 :: "l"(addr), "f"(v.x), "f"(v.y), "f"(v.z), "f"(v.w)
                 : "memory");
}

__global__ void scatter2_kernel(const int* __restrict__ ei) {
    int e = blockIdx.x * blockDim.x + threadIdx.x;
    if (e >= E_EDGES) return;
    int s = __ldg(&ei[e]);
    int d = __ldg(&ei[E_EDGES + e]);
    const float4* yp = (const float4*)&g_y[s * NO];
    float4 va = __ldg(yp);
    float4 vb = __ldg(yp + 1);
    red_add_v4(&g_acc[d * NO], va);
    red_add_v4(&g_acc[d * NO + 4], vb);
}

// ---------------------------------------------------------------------------
// K5: LSTM scan. 2 independent chains per block (named-barrier groups of
// 4 warps / 128 threads). Per group: thread pair (lanes 2u,2u+1) owns hidden
// unit j = warp*16 + u; lane parity p selects gates {i,f} (p=0) / {g,o} (p=1).
// h kept in a 64-row ring; outputs flushed in bulk every 64 steps.
// ---------------------------------------------------------------------------
#define GBAR(gid) asm volatile("bar.sync %0, 128;" :: "r"((gid) + 1) : "memory")

__global__ void __launch_bounds__(256, 1) lstm_kernel(
    const float* __restrict__ Wih, const float* __restrict__ Whh,
    const float* __restrict__ bih, const float* __restrict__ bhh,
    const float* __restrict__ Wlin, float* __restrict__ out) {
    __shared__ __align__(16) float hring[2][64][68];   // 68-stride: pad for flush
    __shared__ __align__(16) float xtile[2][64 * NO];
    __shared__ float swlin[HH];

    int tid = threadIdx.x;
    int g = tid >> 7;            // group 0/1
    int lt = tid & 127;          // thread within group
    int l = tid & 31;
    int wl = (tid >> 5) & 3;     // warp within group
    int j = wl * 16 + (l >> 1);  // hidden unit
    int p = l & 1;               // gate-pair selector
    int gidxA = (2 * p) * 64 + j;        // p=0: i ; p=1: g
    int gidxB = (2 * p + 1) * 64 + j;    // p=0: f ; p=1: o

    // packed weights over the reduction dim
    unsigned long long whhA[HH / 2], whhB[HH / 2];
    #pragma unroll
    for (int k = 0; k < HH / 2; k++) {
        whhA[k] = pack2(__ldg(&Whh[(2 * k) * 256 + gidxA]),
                        __ldg(&Whh[(2 * k + 1) * 256 + gidxA]));
        whhB[k] = pack2(__ldg(&Whh[(2 * k) * 256 + gidxB]),
                        __ldg(&Whh[(2 * k + 1) * 256 + gidxB]));
    }
    unsigned long long wihA[NO / 2], wihB[NO / 2];
    #pragma unroll
    for (int k = 0; k < NO / 2; k++) {
        wihA[k] = pack2(__ldg(&Wih[(2 * k) * 256 + gidxA]),
                        __ldg(&Wih[(2 * k + 1) * 256 + gidxA]));
        wihB[k] = pack2(__ldg(&Wih[(2 * k) * 256 + gidxB]),
                        __ldg(&Wih[(2 * k + 1) * 256 + gidxB]));
    }
    float bA = __ldg(&bih[gidxA]) + __ldg(&bhh[gidxA]);
    float bB = __ldg(&bih[gidxB]) + __ldg(&bhh[gidxB]);

    // zero this group's ring; load Wlin
    for (int k = lt; k < 64 * 68; k += 128)
        ((float*)hring[g])[k] = 0.f;
    if (tid < HH) swlin[tid] = __ldg(&Wlin[tid]);
    __syncthreads();   // whole block once; groups independent afterwards

    int chunk = blockIdx.x * 2 + g;
    int start = chunk * CHUNK;
    if (start >= N_NODES) return;
    int end = start + CHUNK;
    if (end > N_NODES) end = N_NODES;
    int s0 = start - LOOKBACK;
    if (s0 < 0) s0 = 0;

    float c = 0.f;

    for (int n = s0; n < end; n++) {
        int r = n & 63;
        if (r == 0 || n == s0) {
            int w0 = n & ~63;
            #pragma unroll
            for (int q = 0; q < 4; q++)
                xtile[g][lt + 128 * q] = g_acc[w0 * NO + lt + 128 * q];
            GBAR(g);
        }
        // gate pre-activations (packed)
        const ulonglong2* xp = (const ulonglong2*)&xtile[g][r * NO];
        ulonglong2 xv0 = xp[0];
        ulonglong2 xv1 = xp[1];
        unsigned long long aA0 = pack2(bA, 0.f), aA1 = pack2(0.f, 0.f);
        unsigned long long aB0 = pack2(bB, 0.f), aB1 = pack2(0.f, 0.f);
        aA0 = fma2(xv0.x, wihA[0], aA0); aA1 = fma2(xv0.y, wihA[1], aA1);
        aA0 = fma2(xv1.x, wihA[2], aA0); aA1 = fma2(xv1.y, wihA[3], aA1);
        aB0 = fma2(xv0.x, wihB[0], aB0); aB1 = fma2(xv0.y, wihB[1], aB1);
        aB0 = fma2(xv1.x, wihB[2], aB0); aB1 = fma2(xv1.y, wihB[3], aB1);
        const ulonglong2* hp = (const ulonglong2*)hring[g][(n - 1) & 63];
        #pragma unroll
        for (int k = 0; k < 16; k++) {
            ulonglong2 hv = hp[k];   // broadcast LDS.128
            aA0 = fma2(hv.x, whhA[2 * k + 0], aA0);
            aA1 = fma2(hv.y, whhA[2 * k + 1], aA1);
            aB0 = fma2(hv.x, whhB[2 * k + 0], aB0);
            aB1 = fma2(hv.y, whhB[2 * k + 1], aB1);
        }
        float aA = unpack_sum(aA0) + unpack_sum(aA1);
        float aB = unpack_sum(aB0) + unpack_sum(aB1);
        // p=0: actA=sigmoid(i), actB=sigmoid(f) ; p=1: actA=tanh(g), actB=sigmoid(o)
        float tA = tanh_a(p ? aA : 0.5f * aA);
        float actA = p ? tA : fmaf(0.5f, tA, 0.5f);
        float tB = tanh_a(0.5f * aB);
        float actB = fmaf(0.5f, tB, 0.5f);
        float rAv = __shfl_xor_sync(0xffffffffu, actA, 1);
        float rBv = __shfl_xor_sync(0xffffffffu, actB, 1);
        float iv = p ? rAv : actA;
        float fv = p ? rBv : actB;
        float gv = p ? actA : rAv;
        float ov = p ? actB : rBv;
        c = fmaf(fv, c, iv * gv);          // both lanes keep identical c
        float hn = ov * tanh_a(c);
        if (p == 0) hring[g][r][j] = hn;
        GBAR(g);

        if (r == 63 || n == end - 1) {
            // bulk output flush for window [w0, w0+64) ∩ [start, end)
            int w0 = n & ~63;
            int nn = w0 + (lt >> 1);
            int half = lt & 1;
            const float* hrow = hring[g][lt >> 1];
            float acc = 0.f;
            #pragma unroll
            for (int k = 0; k < 32; k++)
                acc = fmaf(hrow[half * 32 + k], swlin[half * 32 + k], acc);
            acc += __shfl_xor_sync(0xffffffffu, acc, 1);
            if (half == 0 && nn >= start && nn < end)
                out[nn] += acc;            // exclusive writer; out pre-set to wt
        }
    }
}

// ---------------------------------------------------------------------------
extern "C" void kernel_launch(void* const* d_in, const int* in_sizes, int n_in,
                              void* d_out, int out_size) {
    const float* x        = (const float*)d_in[0];
    const int*   ei       = (const int*)  d_in[1];
    const float* weather  = (const float*)d_in[2];
    const float* timeenc  = (const float*)d_in[3];
    const float* W1rel    = (const float*)d_in[4];
    const float* b1       = (const float*)d_in[5];
    const float* W1root   = (const float*)d_in[6];
    const float* W2rel    = (const float*)d_in[7];
    const float* b2       = (const float*)d_in[8];
    const float* W2root   = (const float*)d_in[9];
    const float* Wih      = (const float*)d_in[10];
    const float* Whh      = (const float*)d_in[11];
    const float* bih      = (const float*)d_in[12];
    const float* bhh      = (const float*)d_in[13];
    const float* Wlin     = (const float*)d_in[14];
    const float* blin     = (const float*)d_in[15];
    float* out = (float*)d_out;

    prep_kernel<<<(N_NODES + 255) / 256, 256>>>(x, weather, timeenc, Wlin, blin);
    scatter1_kernel<<<(E_EDGES / 4 + 255) / 256, 256>>>(ei);
    node_kernel<<<(N_NODES + 255) / 256, 256>>>(W1rel, b1, W1root, W2rel, b2, W2root, out);
    scatter2_kernel<<<(E_EDGES + 255) / 256, 256>>>(ei);
    lstm_kernel<<<NBLK, 256>>>(Wih, Whh, bih, bhh, Wlin, out);
}